// round 6
// baseline (speedup 1.0000x reference)
#include <cuda_runtime.h>
#include <cstdint>
#include <cstddef>

// Problem constants
#define BB   8
#define SS   2048
#define NN   8
#define HH   1024
#define DD   64
#define TEMP 50.0f
#define CH   64      // S-chunks for pooling
#define SCH  32      // S per chunk (CH*SCH == SS)

// ---------------- device scratch (allocation-free: __device__ globals) -----
__device__ float g_qpart[BB][CH][HH];
__device__ float g_kpart[BB][CH][NN * DD];
__device__ float g_lenpart[BB][CH];
__device__ float g_qsent[BB][HH];
__device__ float g_ksent[BB][NN * DD];
__device__ float g_qenc[BB][DD];
__device__ float g_kenc[BB][NN * DD];
__device__ float g_probs[BB][NN];
__device__ float g_vmix[(size_t)BB * SS * HH];   // 64 MB, tf32-rounded fp32
__device__ float g_wvr[HH * HH];                 // 4 MB, tf32-rounded Wv

__device__ __forceinline__ float tf32_rna(float x) {
    uint32_t u;
    asm("cvt.rna.tf32.f32 %0, %1;" : "=r"(u) : "f"(x));
    return __uint_as_float(u);
}

__device__ __forceinline__ float warp_sum(float v) {
    #pragma unroll
    for (int o = 16; o > 0; o >>= 1) v += __shfl_xor_sync(0xFFFFFFFFu, v, o);
    return v;
}

// ---------------- 1) masked-pool partials + Wv tf32 rounding (fused grid) ---
__global__ void k_pool_round(const float* __restrict__ query,
                             const float* __restrict__ key,
                             const int* __restrict__ amask,
                             const float* __restrict__ Wv) {
    const int blk = blockIdx.x;
    const int tid = threadIdx.x;
    if (blk >= BB * CH) {
        // Wv rounding part: blocks [512, 1536) -> 1024 blocks x 256 threads
        const int i = (blk - BB * CH) * 256 + tid;   // float4 index, 262144 total
        float4 v = ((const float4*)Wv)[i];
        v.x = tf32_rna(v.x); v.y = tf32_rna(v.y);
        v.z = tf32_rna(v.z); v.w = tf32_rna(v.w);
        ((float4*)g_wvr)[i] = v;
        return;
    }
    const int b = blk >> 6, c = blk & 63;
    const int s0 = c * SCH;
    __shared__ float sm[SCH];
    if (tid < SCH)
        sm[tid] = (amask[b * SS + s0 + tid] == 0) ? 1.0f : 0.0f;
    __syncthreads();
    if (tid == 0) {
        float l = 0.f;
        #pragma unroll
        for (int s = 0; s < SCH; s++) l += sm[s];
        g_lenpart[b][c] = l;
    }
    float aq[4] = {0.f, 0.f, 0.f, 0.f};
    float ak[2] = {0.f, 0.f};
    for (int s = 0; s < SCH; s++) {
        const float m = sm[s];
        const float* qrow = query + (size_t)(b * SS + s0 + s) * HH;
        const float* krow = key   + (size_t)(b * SS + s0 + s) * (NN * DD);
        #pragma unroll
        for (int j = 0; j < 4; j++) aq[j] += m * qrow[tid + j * 256];
        #pragma unroll
        for (int j = 0; j < 2; j++) ak[j] += m * krow[tid + j * 256];
    }
    #pragma unroll
    for (int j = 0; j < 4; j++) g_qpart[b][c][tid + j * 256] = aq[j];
    #pragma unroll
    for (int j = 0; j < 2; j++) g_kpart[b][c][tid + j * 256] = ak[j];
}

// ---------------- 2) combine partials -> pooled means (distributed) --------
__global__ void k_combine() {
    const int tid = blockIdx.x * 256 + threadIdx.x;
    __shared__ float s_inv[BB];
    if (threadIdx.x < BB) {
        float l = 0.f;
        #pragma unroll
        for (int c = 0; c < CH; c++) l += g_lenpart[threadIdx.x][c];
        s_inv[threadIdx.x] = 1.0f / l;
    }
    __syncthreads();
    if (tid < 2048) {            // query columns
        const int b = tid >> 8, c4 = tid & 255;
        float4 a = make_float4(0.f, 0.f, 0.f, 0.f);
        #pragma unroll 4
        for (int c = 0; c < CH; c++) {
            const float4 v = ((const float4*)g_qpart[b][c])[c4];
            a.x += v.x; a.y += v.y; a.z += v.z; a.w += v.w;
        }
        const float inv = s_inv[b];
        a.x *= inv; a.y *= inv; a.z *= inv; a.w *= inv;
        ((float4*)g_qsent[b])[c4] = a;
    } else {                     // key columns
        const int t = tid - 2048;
        const int b = t >> 7, c4 = t & 127;
        float4 a = make_float4(0.f, 0.f, 0.f, 0.f);
        #pragma unroll 4
        for (int c = 0; c < CH; c++) {
            const float4 v = ((const float4*)g_kpart[b][c])[c4];
            a.x += v.x; a.y += v.y; a.z += v.z; a.w += v.w;
        }
        const float inv = s_inv[b];
        a.x *= inv; a.y *= inv; a.z *= inv; a.w *= inv;
        ((float4*)g_ksent[b])[c4] = a;
    }
}

// ---------------- 3) encoders (distributed, warp per dot) -------------------
__global__ void k_enc(const float* __restrict__ Wq,
                      const float* __restrict__ bq,
                      const float* __restrict__ Wk,
                      const float* __restrict__ bk) {
    const int blk = blockIdx.x;
    const int w = threadIdx.x >> 5, lane = threadIdx.x & 31;
    if (blk < 64) {
        const int dot = blk * 8 + w;
        const int b = dot >> 6, dd = dot & 63;
        const float* qs = g_qsent[b];
        const float* wq = Wq + (size_t)dd * HH;
        float a = 0.f;
        #pragma unroll
        for (int j = 0; j < HH / 32; j++) {
            const int h = lane + j * 32;
            a += qs[h] * wq[h];
        }
        a = warp_sum(a);
        if (lane == 0) g_qenc[b][dd] = a + bq[dd];
    } else {
        const int base = (blk - 64) * 256 + w * 32;
        #pragma unroll 1
        for (int i = 0; i < 32; i++) {
            const int dot = base + i;
            const int b = dot >> 9, n = (dot >> 6) & 7, dd = dot & 63;
            const float* ks = &g_ksent[b][n * DD];
            const float* wk = Wk + dd * DD;
            float a = ks[lane] * wk[lane] + ks[lane + 32] * wk[lane + 32];
            a = warp_sum(a);
            if (lane == 0) g_kenc[b][n * DD + dd] = a + bk[dd];
        }
    }
}

// ---------------- 4) scores + softmax (tiny) --------------------------------
__global__ void k_softmax() {
    __shared__ float s_sc[BB * NN];
    const int tid = threadIdx.x;
    if (tid < BB * NN) {
        const int b = tid >> 3, n = tid & 7;
        float a = 0.f;
        const float* ke = &g_kenc[b][n * DD];
        const float* qe = g_qenc[b];
        #pragma unroll
        for (int d = 0; d < DD; d++) a += ke[d] * qe[d];
        s_sc[tid] = a * (1.0f / TEMP);
    }
    __syncthreads();
    if (tid < BB) {
        const int b = tid;
        float mx = -1e30f;
        #pragma unroll
        for (int n = 0; n < NN; n++) mx = fmaxf(mx, s_sc[b * NN + n]);
        float e[NN], sum = 0.f;
        #pragma unroll
        for (int n = 0; n < NN; n++) { e[n] = expf(s_sc[b * NN + n] - mx); sum += e[n]; }
        const float isum = 1.0f / sum;
        #pragma unroll
        for (int n = 0; n < NN; n++) g_probs[b][n] = e[n] * isum;
    }
}

// ---------------- 5) vmix[b,s,h] = sum_n probs[b,n] * value[b,s,n,h] --------
__global__ void k_vmix(const float* __restrict__ value) {
    const int r0 = blockIdx.x * 16;          // 1024 blocks
    const int b = blockIdx.x >> 7;           // 128 blocks per batch
    const int tid = threadIdx.x;             // 256 threads: one float4 col each
    __shared__ float sp[NN];
    if (tid < NN) sp[tid] = g_probs[b][tid];
    __syncthreads();
    #pragma unroll
    for (int rp = 0; rp < 8; rp++) {
        const size_t row0 = (size_t)(r0 + rp * 2);
        const size_t row1 = row0 + 1;
        const float4* vp0 = (const float4*)(value + row0 * (NN * HH));
        const float4* vp1 = (const float4*)(value + row1 * (NN * HH));
        float4 a0 = make_float4(0.f, 0.f, 0.f, 0.f);
        float4 a1 = make_float4(0.f, 0.f, 0.f, 0.f);
        #pragma unroll
        for (int n = 0; n < NN; n++) {
            const float4 v0 = vp0[n * (HH / 4) + tid];
            const float4 v1 = vp1[n * (HH / 4) + tid];
            const float p = sp[n];
            a0.x += p * v0.x; a0.y += p * v0.y; a0.z += p * v0.z; a0.w += p * v0.w;
            a1.x += p * v1.x; a1.y += p * v1.y; a1.z += p * v1.z; a1.w += p * v1.w;
        }
        a0.x = tf32_rna(a0.x); a0.y = tf32_rna(a0.y);
        a0.z = tf32_rna(a0.z); a0.w = tf32_rna(a0.w);
        a1.x = tf32_rna(a1.x); a1.y = tf32_rna(a1.y);
        a1.z = tf32_rna(a1.z); a1.w = tf32_rna(a1.w);
        ((float4*)g_vmix)[row0 * (HH / 4) + tid] = a0;
        ((float4*)g_vmix)[row1 * (HH / 4) + tid] = a1;
    }
}

// ---------------- 6) GEMM: out = vmix @ Wv^T + bv (tf32 mma.sync) -----------
// 4-stage cp.async pipeline, ldmatrix fragment loads, one barrier per k-tile.
#define BM 128
#define BN 128
#define BK 16
#define LDA 20                 // padded smem stride (conflict-free for LDSM)
#define KT (HH / BK)           // 64
#define NST 4
#define STG_A (BM * LDA)       // floats per A stage
#define STG_B (BN * LDA)
#define GSMEM (NST * (STG_A + STG_B) * 4)   // 81920 bytes

__device__ __forceinline__ void cp_async16(uint32_t s, const void* g) {
    asm volatile("cp.async.cg.shared.global [%0], [%1], 16;" :: "r"(s), "l"(g));
}
__device__ __forceinline__ void ldsm_x4(uint32_t& d0, uint32_t& d1,
                                        uint32_t& d2, uint32_t& d3, uint32_t a) {
    asm volatile("ldmatrix.sync.aligned.m8n8.x4.shared.b16 {%0,%1,%2,%3}, [%4];"
                 : "=r"(d0), "=r"(d1), "=r"(d2), "=r"(d3) : "r"(a));
}

__global__ __launch_bounds__(256, 2) void k_gemm(const float* __restrict__ bias,
                                                 float* __restrict__ C) {
    extern __shared__ float smemf[];
    float* As = smemf;                  // [NST][STG_A]
    float* Bs = smemf + NST * STG_A;    // [NST][STG_B]
    const int tid = threadIdx.x;
    const int m0 = blockIdx.y * BM, n0 = blockIdx.x * BN;
    const int warp = tid >> 5, lane = tid & 31;
    const int wm = warp >> 2, wn = warp & 3;    // 2 x 4 warp grid
    const int grp = lane >> 2, qid = lane & 3;

    // cp.async addressing: each thread moves 2 x 16B for A and B per stage
    const int ldr = tid >> 2;            // 0..63
    const int ldc = (tid & 3) * 4;       // 0,4,8,12
    const float* Ag0 = g_vmix + (size_t)(m0 + ldr) * HH + ldc;
    const float* Ag1 = Ag0 + (size_t)64 * HH;
    const float* Bg0 = g_wvr + (size_t)(n0 + ldr) * HH + ldc;
    const float* Bg1 = Bg0 + (size_t)64 * HH;
    const uint32_t sa0 = (uint32_t)__cvta_generic_to_shared(&As[ldr * LDA + ldc]);
    const uint32_t sa1 = (uint32_t)__cvta_generic_to_shared(&As[(ldr + 64) * LDA + ldc]);
    const uint32_t sb0 = (uint32_t)__cvta_generic_to_shared(&Bs[ldr * LDA + ldc]);
    const uint32_t sb1 = (uint32_t)__cvta_generic_to_shared(&Bs[(ldr + 64) * LDA + ldc]);
    const uint32_t stA = sizeof(float) * STG_A;
    const uint32_t stB = sizeof(float) * STG_B;

    // ldmatrix per-thread address bases:
    // A matrices: j=0:(r,c) j=1:(r+8,c) j=2:(r,c+4) j=3:(r+8,c+4)
    // B matrices: j=0:(n,c) j=1:(n,c+4) j=2:(n+8,c) j=3:(n+8,c+4)
    const int rw = lane & 7, jm = lane >> 3;
    const int a_ro = ((jm & 1) << 3) + rw, a_co = (jm >> 1) << 2;
    const int b_ro = ((jm >> 1) << 3) + rw, b_co = (jm & 1) << 2;
    const uint32_t aF = (uint32_t)__cvta_generic_to_shared(
        &As[(wm * 64 + a_ro) * LDA + a_co]);
    const uint32_t bF = (uint32_t)__cvta_generic_to_shared(
        &Bs[(wn * 32 + b_ro) * LDA + b_co]);

    float acc[4][4][4];
    #pragma unroll
    for (int i = 0; i < 4; i++)
        #pragma unroll
        for (int j = 0; j < 4; j++)
            #pragma unroll
            for (int v = 0; v < 4; v++) acc[i][j][v] = 0.f;

    // prologue: stages 0,1,2 in flight
    #pragma unroll
    for (int s = 0; s < 3; s++) {
        const int kb = s * BK;
        cp_async16(sa0 + s * stA, Ag0 + kb); cp_async16(sa1 + s * stA, Ag1 + kb);
        cp_async16(sb0 + s * stB, Bg0 + kb); cp_async16(sb1 + s * stB, Bg1 + kb);
        asm volatile("cp.async.commit_group;");
    }

    #pragma unroll 1
    for (int kt = 0; kt < KT; kt++) {
        const int st = kt & (NST - 1);
        asm volatile("cp.async.wait_group 2;");
        __syncthreads();   // stage (kt+3)&3 was consumed at iter kt-1 by all warps

        if (kt + 3 < KT) {
            const int s2 = (kt + 3) & (NST - 1);
            const int kb = (kt + 3) * BK;
            cp_async16(sa0 + s2 * stA, Ag0 + kb); cp_async16(sa1 + s2 * stA, Ag1 + kb);
            cp_async16(sb0 + s2 * stB, Bg0 + kb); cp_async16(sb1 + s2 * stB, Bg1 + kb);
        }
        asm volatile("cp.async.commit_group;");

        const uint32_t aS = aF + st * stA;
        const uint32_t bS = bF + st * stB;
        #pragma unroll
        for (int ks = 0; ks < 2; ks++) {
            uint32_t af[4][4], bf[4][2];
            #pragma unroll
            for (int mf = 0; mf < 4; mf++)
                ldsm_x4(af[mf][0], af[mf][1], af[mf][2], af[mf][3],
                        aS + (uint32_t)((mf * 16 * LDA + ks * 8) * 4));
            #pragma unroll
            for (int np = 0; np < 2; np++)
                ldsm_x4(bf[2 * np][0], bf[2 * np][1], bf[2 * np + 1][0], bf[2 * np + 1][1],
                        bS + (uint32_t)((np * 16 * LDA + ks * 8) * 4));
            #pragma unroll
            for (int mf = 0; mf < 4; mf++)
                #pragma unroll
                for (int nf = 0; nf < 4; nf++) {
                    asm volatile(
                        "mma.sync.aligned.m16n8k8.row.col.f32.tf32.tf32.f32 "
                        "{%0,%1,%2,%3}, {%4,%5,%6,%7}, {%8,%9}, {%0,%1,%2,%3};"
                        : "+f"(acc[mf][nf][0]), "+f"(acc[mf][nf][1]),
                          "+f"(acc[mf][nf][2]), "+f"(acc[mf][nf][3])
                        : "r"(af[mf][0]), "r"(af[mf][1]), "r"(af[mf][2]), "r"(af[mf][3]),
                          "r"(bf[nf][0]), "r"(bf[nf][1]));
                }
        }
    }

    // epilogue: + bias, float2 stores
    #pragma unroll
    for (int mf = 0; mf < 4; mf++) {
        const int r = m0 + wm * 64 + mf * 16 + grp;
        #pragma unroll
        for (int nf = 0; nf < 4; nf++) {
            const int c = n0 + wn * 32 + nf * 8 + qid * 2;
            const float b0v = __ldg(bias + c);
            const float b1v = __ldg(bias + c + 1);
            float2 v0 = make_float2(acc[mf][nf][0] + b0v, acc[mf][nf][1] + b1v);
            float2 v1 = make_float2(acc[mf][nf][2] + b0v, acc[mf][nf][3] + b1v);
            *(float2*)(C + (size_t)r * HH + c) = v0;
            *(float2*)(C + (size_t)(r + 8) * HH + c) = v1;
        }
    }
}

// ---------------- launch -----------------------------------------------------
extern "C" void kernel_launch(void* const* d_in, const int* in_sizes, int n_in,
                              void* d_out, int out_size) {
    (void)in_sizes; (void)n_in; (void)out_size;
    const float* query = (const float*)d_in[0];
    const float* key   = (const float*)d_in[1];
    const float* value = (const float*)d_in[2];
    const int*   amask = (const int*)d_in[3];
    const float* Wq    = (const float*)d_in[4];
    const float* bq    = (const float*)d_in[5];
    const float* Wk    = (const float*)d_in[6];
    const float* bk    = (const float*)d_in[7];
    const float* Wv    = (const float*)d_in[8];
    const float* bv    = (const float*)d_in[9];
    float* out = (float*)d_out;

    static int smem_set = 0;
    if (!smem_set) {
        cudaFuncSetAttribute(k_gemm, cudaFuncAttributeMaxDynamicSharedMemorySize, GSMEM);
        smem_set = 1;
    }

    k_pool_round<<<BB * CH + HH * HH / (4 * 256), 256>>>(query, key, amask, Wv);
    k_combine<<<12, 256>>>();
    k_enc<<<80, 256>>>(Wq, bq, Wk, bk);
    k_softmax<<<1, 64>>>();
    k_vmix<<<BB * SS / 16, 256>>>(value);
    k_gemm<<<dim3(HH / BN, BB * SS / BM), 256, GSMEM>>>(bv, out);
}

// round 7
// speedup vs baseline: 1.4600x; 1.4600x over previous
#include <cuda_runtime.h>
#include <cstdint>
#include <cstddef>

// Problem constants
#define BB   8
#define SS   2048
#define NN   8
#define HH   1024
#define DD   64
#define TEMP 50.0f
#define CH   64      // S-chunks for pooling
#define SCH  32      // S per chunk (CH*SCH == SS)

// ---------------- device scratch (allocation-free: __device__ globals) -----
__device__ float g_qpart[BB][CH][HH];
__device__ float g_kpart[BB][CH][NN * DD];
__device__ float g_lenpart[BB][CH];
__device__ float g_qsent[BB][HH];
__device__ float g_ksent[BB][NN * DD];
__device__ float g_qenc[BB][DD];
__device__ float g_kenc[BB][NN * DD];
__device__ float g_vmix[(size_t)BB * SS * HH];   // 64 MB, tf32-rounded fp32
__device__ float g_wvr[HH * HH];                 // 4 MB, tf32-rounded Wv

__device__ __forceinline__ float tf32_rna(float x) {
    uint32_t u;
    asm("cvt.rna.tf32.f32 %0, %1;" : "=r"(u) : "f"(x));
    return __uint_as_float(u);
}

__device__ __forceinline__ float warp_sum(float v) {
    #pragma unroll
    for (int o = 16; o > 0; o >>= 1) v += __shfl_xor_sync(0xFFFFFFFFu, v, o);
    return v;
}

// ---------------- 1) masked-pool partials + Wv tf32 rounding (fused grid) ---
__global__ void k_pool_round(const float* __restrict__ query,
                             const float* __restrict__ key,
                             const int* __restrict__ amask,
                             const float* __restrict__ Wv) {
    const int blk = blockIdx.x;
    const int tid = threadIdx.x;
    if (blk >= BB * CH) {
        const int i = (blk - BB * CH) * 256 + tid;   // float4 index, 262144 total
        float4 v = ((const float4*)Wv)[i];
        v.x = tf32_rna(v.x); v.y = tf32_rna(v.y);
        v.z = tf32_rna(v.z); v.w = tf32_rna(v.w);
        ((float4*)g_wvr)[i] = v;
        return;
    }
    const int b = blk >> 6, c = blk & 63;
    const int s0 = c * SCH;
    __shared__ float sm[SCH];
    if (tid < SCH)
        sm[tid] = (amask[b * SS + s0 + tid] == 0) ? 1.0f : 0.0f;
    __syncthreads();
    if (tid == 0) {
        float l = 0.f;
        #pragma unroll
        for (int s = 0; s < SCH; s++) l += sm[s];
        g_lenpart[b][c] = l;
    }
    float aq[4] = {0.f, 0.f, 0.f, 0.f};
    float ak[2] = {0.f, 0.f};
    for (int s = 0; s < SCH; s++) {
        const float m = sm[s];
        const float* qrow = query + (size_t)(b * SS + s0 + s) * HH;
        const float* krow = key   + (size_t)(b * SS + s0 + s) * (NN * DD);
        #pragma unroll
        for (int j = 0; j < 4; j++) aq[j] += m * qrow[tid + j * 256];
        #pragma unroll
        for (int j = 0; j < 2; j++) ak[j] += m * krow[tid + j * 256];
    }
    #pragma unroll
    for (int j = 0; j < 4; j++) g_qpart[b][c][tid + j * 256] = aq[j];
    #pragma unroll
    for (int j = 0; j < 2; j++) g_kpart[b][c][tid + j * 256] = ak[j];
}

// ---------------- 2) combine partials -> pooled means (distributed) --------
__global__ void k_combine() {
    const int tid = blockIdx.x * 256 + threadIdx.x;
    __shared__ float s_inv[BB];
    if (threadIdx.x < BB) {
        float l = 0.f;
        #pragma unroll
        for (int c = 0; c < CH; c++) l += g_lenpart[threadIdx.x][c];
        s_inv[threadIdx.x] = 1.0f / l;
    }
    __syncthreads();
    if (tid < 2048) {            // query columns
        const int b = tid >> 8, c4 = tid & 255;
        float4 a = make_float4(0.f, 0.f, 0.f, 0.f);
        #pragma unroll 4
        for (int c = 0; c < CH; c++) {
            const float4 v = ((const float4*)g_qpart[b][c])[c4];
            a.x += v.x; a.y += v.y; a.z += v.z; a.w += v.w;
        }
        const float inv = s_inv[b];
        a.x *= inv; a.y *= inv; a.z *= inv; a.w *= inv;
        ((float4*)g_qsent[b])[c4] = a;
    } else {                     // key columns
        const int t = tid - 2048;
        const int b = t >> 7, c4 = t & 127;
        float4 a = make_float4(0.f, 0.f, 0.f, 0.f);
        #pragma unroll 4
        for (int c = 0; c < CH; c++) {
            const float4 v = ((const float4*)g_kpart[b][c])[c4];
            a.x += v.x; a.y += v.y; a.z += v.z; a.w += v.w;
        }
        const float inv = s_inv[b];
        a.x *= inv; a.y *= inv; a.z *= inv; a.w *= inv;
        ((float4*)g_ksent[b])[c4] = a;
    }
}

// ---------------- 3) encoders (distributed, warp per dot) -------------------
__global__ void k_enc(const float* __restrict__ Wq,
                      const float* __restrict__ bq,
                      const float* __restrict__ Wk,
                      const float* __restrict__ bk) {
    const int blk = blockIdx.x;
    const int w = threadIdx.x >> 5, lane = threadIdx.x & 31;
    if (blk < 64) {
        const int dot = blk * 8 + w;
        const int b = dot >> 6, dd = dot & 63;
        const float* qs = g_qsent[b];
        const float* wq = Wq + (size_t)dd * HH;
        float a = 0.f;
        #pragma unroll
        for (int j = 0; j < HH / 32; j++) {
            const int h = lane + j * 32;
            a += qs[h] * wq[h];
        }
        a = warp_sum(a);
        if (lane == 0) g_qenc[b][dd] = a + bq[dd];
    } else {
        const int base = (blk - 64) * 256 + w * 32;
        #pragma unroll 1
        for (int i = 0; i < 32; i++) {
            const int dot = base + i;
            const int b = dot >> 9, n = (dot >> 6) & 7, dd = dot & 63;
            const float* ks = &g_ksent[b][n * DD];
            const float* wk = Wk + dd * DD;
            float a = ks[lane] * wk[lane] + ks[lane + 32] * wk[lane + 32];
            a = warp_sum(a);
            if (lane == 0) g_kenc[b][n * DD + dd] = a + bk[dd];
        }
    }
}

// ---------------- 4) vmix (+ inline softmax) --------------------------------
// vmix[b,s,h] = sum_n probs[b,n] * value[b,s,n,h]; probs recomputed per block.
__global__ void k_vmix(const float* __restrict__ value) {
    const int r0 = blockIdx.x * 16;          // 1024 blocks
    const int b = blockIdx.x >> 7;           // 128 blocks per batch
    const int tid = threadIdx.x;             // 256 threads: one float4 col each
    __shared__ float sp[NN];
    __shared__ float ssc[NN];
    if (tid < NN) {
        float a = 0.f;
        const float* ke = &g_kenc[b][tid * DD];
        const float* qe = g_qenc[b];
        #pragma unroll
        for (int d = 0; d < DD; d++) a += ke[d] * qe[d];
        ssc[tid] = a * (1.0f / TEMP);
    }
    __syncthreads();
    if (tid == 0) {
        float mx = -1e30f;
        #pragma unroll
        for (int n = 0; n < NN; n++) mx = fmaxf(mx, ssc[n]);
        float e[NN], sum = 0.f;
        #pragma unroll
        for (int n = 0; n < NN; n++) { e[n] = expf(ssc[n] - mx); sum += e[n]; }
        const float isum = 1.0f / sum;
        #pragma unroll
        for (int n = 0; n < NN; n++) sp[n] = e[n] * isum;
    }
    __syncthreads();
    #pragma unroll
    for (int rp = 0; rp < 8; rp++) {
        const size_t row0 = (size_t)(r0 + rp * 2);
        const size_t row1 = row0 + 1;
        const float4* vp0 = (const float4*)(value + row0 * (NN * HH));
        const float4* vp1 = (const float4*)(value + row1 * (NN * HH));
        float4 a0 = make_float4(0.f, 0.f, 0.f, 0.f);
        float4 a1 = make_float4(0.f, 0.f, 0.f, 0.f);
        #pragma unroll
        for (int n = 0; n < NN; n++) {
            const float4 v0 = __ldcs(vp0 + n * (HH / 4) + tid);
            const float4 v1 = __ldcs(vp1 + n * (HH / 4) + tid);
            const float p = sp[n];
            a0.x += p * v0.x; a0.y += p * v0.y; a0.z += p * v0.z; a0.w += p * v0.w;
            a1.x += p * v1.x; a1.y += p * v1.y; a1.z += p * v1.z; a1.w += p * v1.w;
        }
        a0.x = tf32_rna(a0.x); a0.y = tf32_rna(a0.y);
        a0.z = tf32_rna(a0.z); a0.w = tf32_rna(a0.w);
        a1.x = tf32_rna(a1.x); a1.y = tf32_rna(a1.y);
        a1.z = tf32_rna(a1.z); a1.w = tf32_rna(a1.w);
        ((float4*)g_vmix)[row0 * (HH / 4) + tid] = a0;
        ((float4*)g_vmix)[row1 * (HH / 4) + tid] = a1;
    }
}

// ---------------- 5) GEMM: out = vmix @ Wv^T + bv (tf32 mma.sync) -----------
// 3-stage cp.async pipeline, BK=32 (half as many barriers as BK=16),
// scalar-LDS fragment loads (proven R5 pattern), one barrier per k-tile.
#define BM 128
#define BN 128
#define BK 32
#define LDA 36                 // padded smem stride: bank = 4*grp+qid, conflict-free
#define KT (HH / BK)           // 32
#define NST 3
#define STG_A (BM * LDA)       // floats per A stage
#define STG_B (BN * LDA)
#define GSMEM (NST * (STG_A + STG_B) * 4)   // 110592 bytes

__device__ __forceinline__ void cp_async16(uint32_t s, const void* g) {
    asm volatile("cp.async.cg.shared.global [%0], [%1], 16;" :: "r"(s), "l"(g));
}

__global__ __launch_bounds__(256, 2) void k_gemm(const float* __restrict__ bias,
                                                 float* __restrict__ C) {
    extern __shared__ float smemf[];
    float* As = smemf;                  // [NST][STG_A]
    float* Bs = smemf + NST * STG_A;    // [NST][STG_B]
    const int tid = threadIdx.x;
    const int m0 = blockIdx.y * BM, n0 = blockIdx.x * BN;
    const int warp = tid >> 5, lane = tid & 31;
    const int wm = warp >> 2, wn = warp & 3;    // 2 x 4 warp grid
    const int grp = lane >> 2, qid = lane & 3;

    // cp.async addressing: rows r = (tid>>3) + 32k (k=0..3), col chunk = tid&7
    const int ldr = tid >> 3;            // 0..31
    const int ldc = (tid & 7) * 4;       // 0,4,...,28
    const float* Ag = g_vmix + (size_t)(m0 + ldr) * HH + ldc;
    const float* Bg = g_wvr + (size_t)(n0 + ldr) * HH + ldc;
    const uint32_t sa = (uint32_t)__cvta_generic_to_shared(&As[ldr * LDA + ldc]);
    const uint32_t sb = (uint32_t)__cvta_generic_to_shared(&Bs[ldr * LDA + ldc]);
    const uint32_t stA = sizeof(float) * STG_A;
    const uint32_t stB = sizeof(float) * STG_B;

    float acc[4][4][4];
    #pragma unroll
    for (int i = 0; i < 4; i++)
        #pragma unroll
        for (int j = 0; j < 4; j++)
            #pragma unroll
            for (int v = 0; v < 4; v++) acc[i][j][v] = 0.f;

    // prologue: stages 0 and 1 in flight
    #pragma unroll
    for (int s = 0; s < 2; s++) {
        const int kb = s * BK;
        #pragma unroll
        for (int k = 0; k < 4; k++) {
            cp_async16(sa + s * stA + k * 32 * LDA * 4, Ag + (size_t)k * 32 * HH + kb);
            cp_async16(sb + s * stB + k * 32 * LDA * 4, Bg + (size_t)k * 32 * HH + kb);
        }
        asm volatile("cp.async.commit_group;");
    }

    #pragma unroll 1
    for (int kt = 0; kt < KT; kt++) {
        const int st = kt % NST;
        asm volatile("cp.async.wait_group 1;");
        __syncthreads();   // stage (kt+2)%NST was consumed at iter kt-1 by all warps

        if (kt + 2 < KT) {
            const int s2 = (kt + 2) % NST;
            const int kb = (kt + 2) * BK;
            #pragma unroll
            for (int k = 0; k < 4; k++) {
                cp_async16(sa + s2 * stA + k * 32 * LDA * 4, Ag + (size_t)k * 32 * HH + kb);
                cp_async16(sb + s2 * stB + k * 32 * LDA * 4, Bg + (size_t)k * 32 * HH + kb);
            }
        }
        asm volatile("cp.async.commit_group;");

        const uint32_t* as = (const uint32_t*)(As + st * STG_A);
        const uint32_t* bs = (const uint32_t*)(Bs + st * STG_B);
        #pragma unroll
        for (int ks = 0; ks < 4; ks++) {
            const int kc = ks * 8 + qid;
            uint32_t af[4][4], bf[4][2];
            #pragma unroll
            for (int mf = 0; mf < 4; mf++) {
                const int r = wm * 64 + mf * 16 + grp;
                af[mf][0] = as[r * LDA + kc];
                af[mf][1] = as[(r + 8) * LDA + kc];
                af[mf][2] = as[r * LDA + kc + 4];
                af[mf][3] = as[(r + 8) * LDA + kc + 4];
            }
            #pragma unroll
            for (int nf = 0; nf < 4; nf++) {
                const int n = wn * 32 + nf * 8 + grp;
                bf[nf][0] = bs[n * LDA + kc];
                bf[nf][1] = bs[n * LDA + kc + 4];
            }
            #pragma unroll
            for (int mf = 0; mf < 4; mf++)
                #pragma unroll
                for (int nf = 0; nf < 4; nf++) {
                    asm volatile(
                        "mma.sync.aligned.m16n8k8.row.col.f32.tf32.tf32.f32 "
                        "{%0,%1,%2,%3}, {%4,%5,%6,%7}, {%8,%9}, {%0,%1,%2,%3};"
                        : "+f"(acc[mf][nf][0]), "+f"(acc[mf][nf][1]),
                          "+f"(acc[mf][nf][2]), "+f"(acc[mf][nf][3])
                        : "r"(af[mf][0]), "r"(af[mf][1]), "r"(af[mf][2]), "r"(af[mf][3]),
                          "r"(bf[nf][0]), "r"(bf[nf][1]));
                }
        }
    }

    // epilogue: + bias, float2 stores
    #pragma unroll
    for (int mf = 0; mf < 4; mf++) {
        const int r = m0 + wm * 64 + mf * 16 + grp;
        #pragma unroll
        for (int nf = 0; nf < 4; nf++) {
            const int c = n0 + wn * 32 + nf * 8 + qid * 2;
            const float b0v = __ldg(bias + c);
            const float b1v = __ldg(bias + c + 1);
            float2 v0 = make_float2(acc[mf][nf][0] + b0v, acc[mf][nf][1] + b1v);
            float2 v1 = make_float2(acc[mf][nf][2] + b0v, acc[mf][nf][3] + b1v);
            *(float2*)(C + (size_t)r * HH + c) = v0;
            *(float2*)(C + (size_t)(r + 8) * HH + c) = v1;
        }
    }
}

// ---------------- launch -----------------------------------------------------
extern "C" void kernel_launch(void* const* d_in, const int* in_sizes, int n_in,
                              void* d_out, int out_size) {
    (void)in_sizes; (void)n_in; (void)out_size;
    const float* query = (const float*)d_in[0];
    const float* key   = (const float*)d_in[1];
    const float* value = (const float*)d_in[2];
    const int*   amask = (const int*)d_in[3];
    const float* Wq    = (const float*)d_in[4];
    const float* bq    = (const float*)d_in[5];
    const float* Wk    = (const float*)d_in[6];
    const float* bk    = (const float*)d_in[7];
    const float* Wv    = (const float*)d_in[8];
    const float* bv    = (const float*)d_in[9];
    float* out = (float*)d_out;

    static int smem_set = 0;
    if (!smem_set) {
        cudaFuncSetAttribute(k_gemm, cudaFuncAttributeMaxDynamicSharedMemorySize, GSMEM);
        smem_set = 1;
    }

    k_pool_round<<<BB * CH + HH * HH / (4 * 256), 256>>>(query, key, amask, Wv);
    k_combine<<<12, 256>>>();
    k_enc<<<80, 256>>>(Wq, bq, Wk, bk);
    k_vmix<<<BB * SS / 16, 256>>>(value);
    k_gemm<<<dim3(HH / BN, BB * SS / BM), 256, GSMEM>>>(bv, out);
}

// round 8
// speedup vs baseline: 1.5828x; 1.0841x over previous
#include <cuda_runtime.h>
#include <cstdint>
#include <cstddef>

// Problem constants
#define BB   8
#define SS   2048
#define NN   8
#define HH   1024
#define DD   64
#define TEMP 50.0f
#define CH   64      // S-chunks for pooling
#define SCH  32      // S per chunk (CH*SCH == SS)

// ---------------- device scratch (allocation-free: __device__ globals) -----
__device__ float g_qpart[BB][CH][HH];
__device__ float g_kpart[BB][CH][NN * DD];
__device__ float g_lenpart[BB][CH];
__device__ float g_qsent[BB][HH];
__device__ float g_ksent[BB][NN * DD];
__device__ float g_qenc[BB][DD];
__device__ float g_kenc[BB][NN * DD];
__device__ float g_vmix[(size_t)BB * SS * HH];   // 64 MB, tf32-rounded fp32
__device__ float g_wvr[HH * HH];                 // 4 MB, tf32-rounded Wv

__device__ __forceinline__ float tf32_rna(float x) {
    uint32_t u;
    asm("cvt.rna.tf32.f32 %0, %1;" : "=r"(u) : "f"(x));
    return __uint_as_float(u);
}

__device__ __forceinline__ float warp_sum(float v) {
    #pragma unroll
    for (int o = 16; o > 0; o >>= 1) v += __shfl_xor_sync(0xFFFFFFFFu, v, o);
    return v;
}

// ---------------- 1) masked-pool partials + Wv tf32 rounding (fused grid) ---
__global__ void k_pool_round(const float* __restrict__ query,
                             const float* __restrict__ key,
                             const int* __restrict__ amask,
                             const float* __restrict__ Wv) {
    const int blk = blockIdx.x;
    const int tid = threadIdx.x;
    if (blk >= BB * CH) {
        const int i = (blk - BB * CH) * 256 + tid;   // float4 index, 262144 total
        float4 v = ((const float4*)Wv)[i];
        v.x = tf32_rna(v.x); v.y = tf32_rna(v.y);
        v.z = tf32_rna(v.z); v.w = tf32_rna(v.w);
        ((float4*)g_wvr)[i] = v;
        return;
    }
    const int b = blk >> 6, c = blk & 63;
    const int s0 = c * SCH;
    __shared__ float sm[SCH];
    if (tid < SCH)
        sm[tid] = (amask[b * SS + s0 + tid] == 0) ? 1.0f : 0.0f;
    __syncthreads();
    if (tid == 0) {
        float l = 0.f;
        #pragma unroll
        for (int s = 0; s < SCH; s++) l += sm[s];
        g_lenpart[b][c] = l;
    }
    float aq[4] = {0.f, 0.f, 0.f, 0.f};
    float ak[2] = {0.f, 0.f};
    for (int s = 0; s < SCH; s++) {
        const float m = sm[s];
        const float* qrow = query + (size_t)(b * SS + s0 + s) * HH;
        const float* krow = key   + (size_t)(b * SS + s0 + s) * (NN * DD);
        #pragma unroll
        for (int j = 0; j < 4; j++) aq[j] += m * qrow[tid + j * 256];
        #pragma unroll
        for (int j = 0; j < 2; j++) ak[j] += m * krow[tid + j * 256];
    }
    #pragma unroll
    for (int j = 0; j < 4; j++) g_qpart[b][c][tid + j * 256] = aq[j];
    #pragma unroll
    for (int j = 0; j < 2; j++) g_kpart[b][c][tid + j * 256] = ak[j];
}

// ---------------- 2) combine partials -> pooled means (distributed) --------
__global__ void k_combine() {
    const int tid = blockIdx.x * 256 + threadIdx.x;
    __shared__ float s_inv[BB];
    if (threadIdx.x < BB) {
        float l = 0.f;
        #pragma unroll
        for (int c = 0; c < CH; c++) l += g_lenpart[threadIdx.x][c];
        s_inv[threadIdx.x] = 1.0f / l;
    }
    __syncthreads();
    if (tid < 2048) {            // query columns
        const int b = tid >> 8, c4 = tid & 255;
        float4 a = make_float4(0.f, 0.f, 0.f, 0.f);
        #pragma unroll 4
        for (int c = 0; c < CH; c++) {
            const float4 v = ((const float4*)g_qpart[b][c])[c4];
            a.x += v.x; a.y += v.y; a.z += v.z; a.w += v.w;
        }
        const float inv = s_inv[b];
        a.x *= inv; a.y *= inv; a.z *= inv; a.w *= inv;
        ((float4*)g_qsent[b])[c4] = a;
    } else {                     // key columns
        const int t = tid - 2048;
        const int b = t >> 7, c4 = t & 127;
        float4 a = make_float4(0.f, 0.f, 0.f, 0.f);
        #pragma unroll 4
        for (int c = 0; c < CH; c++) {
            const float4 v = ((const float4*)g_kpart[b][c])[c4];
            a.x += v.x; a.y += v.y; a.z += v.z; a.w += v.w;
        }
        const float inv = s_inv[b];
        a.x *= inv; a.y *= inv; a.z *= inv; a.w *= inv;
        ((float4*)g_ksent[b])[c4] = a;
    }
}

// ---------------- 3) encoders (distributed, warp per dot) -------------------
__global__ void k_enc(const float* __restrict__ Wq,
                      const float* __restrict__ bq,
                      const float* __restrict__ Wk,
                      const float* __restrict__ bk) {
    const int blk = blockIdx.x;
    const int w = threadIdx.x >> 5, lane = threadIdx.x & 31;
    if (blk < 64) {
        const int dot = blk * 8 + w;
        const int b = dot >> 6, dd = dot & 63;
        const float* qs = g_qsent[b];
        const float* wq = Wq + (size_t)dd * HH;
        float a = 0.f;
        #pragma unroll
        for (int j = 0; j < HH / 32; j++) {
            const int h = lane + j * 32;
            a += qs[h] * wq[h];
        }
        a = warp_sum(a);
        if (lane == 0) g_qenc[b][dd] = a + bq[dd];
    } else {
        const int base = (blk - 64) * 256 + w * 32;
        #pragma unroll 1
        for (int i = 0; i < 32; i++) {
            const int dot = base + i;
            const int b = dot >> 9, n = (dot >> 6) & 7, dd = dot & 63;
            const float* ks = &g_ksent[b][n * DD];
            const float* wk = Wk + dd * DD;
            float a = ks[lane] * wk[lane] + ks[lane + 32] * wk[lane + 32];
            a = warp_sum(a);
            if (lane == 0) g_kenc[b][n * DD + dd] = a + bk[dd];
        }
    }
}

// ---------------- 4) vmix (+ inline softmax) --------------------------------
// vmix[b,s,h] = sum_n probs[b,n] * value[b,s,n,h]; probs recomputed per block.
// 16 rows per block, 4 rows interleaved -> 32 independent LDGs in flight.
__global__ void k_vmix(const float* __restrict__ value) {
    const int r0 = blockIdx.x * 16;          // 1024 blocks
    const int b = blockIdx.x >> 7;           // 128 blocks per batch
    const int tid = threadIdx.x;             // 256 threads: one float4 col each
    __shared__ float sp[NN];
    __shared__ float ssc[NN];
    if (tid < NN) {
        float a = 0.f;
        const float* ke = &g_kenc[b][tid * DD];
        const float* qe = g_qenc[b];
        #pragma unroll
        for (int d = 0; d < DD; d++) a += ke[d] * qe[d];
        ssc[tid] = a * (1.0f / TEMP);
    }
    __syncthreads();
    if (tid == 0) {
        float mx = -1e30f;
        #pragma unroll
        for (int n = 0; n < NN; n++) mx = fmaxf(mx, ssc[n]);
        float e[NN], sum = 0.f;
        #pragma unroll
        for (int n = 0; n < NN; n++) { e[n] = expf(ssc[n] - mx); sum += e[n]; }
        const float isum = 1.0f / sum;
        #pragma unroll
        for (int n = 0; n < NN; n++) sp[n] = e[n] * isum;
    }
    __syncthreads();
    #pragma unroll
    for (int rp = 0; rp < 4; rp++) {
        const size_t rb = (size_t)(r0 + rp * 4);
        float4 a0 = make_float4(0.f, 0.f, 0.f, 0.f);
        float4 a1 = a0, a2 = a0, a3 = a0;
        const float4* vp0 = (const float4*)(value + (rb + 0) * (NN * HH));
        const float4* vp1 = (const float4*)(value + (rb + 1) * (NN * HH));
        const float4* vp2 = (const float4*)(value + (rb + 2) * (NN * HH));
        const float4* vp3 = (const float4*)(value + (rb + 3) * (NN * HH));
        #pragma unroll
        for (int n = 0; n < NN; n++) {
            const float p = sp[n];
            const float4 v0 = __ldcs(vp0 + n * (HH / 4) + tid);
            const float4 v1 = __ldcs(vp1 + n * (HH / 4) + tid);
            const float4 v2 = __ldcs(vp2 + n * (HH / 4) + tid);
            const float4 v3 = __ldcs(vp3 + n * (HH / 4) + tid);
            a0.x += p * v0.x; a0.y += p * v0.y; a0.z += p * v0.z; a0.w += p * v0.w;
            a1.x += p * v1.x; a1.y += p * v1.y; a1.z += p * v1.z; a1.w += p * v1.w;
            a2.x += p * v2.x; a2.y += p * v2.y; a2.z += p * v2.z; a2.w += p * v2.w;
            a3.x += p * v3.x; a3.y += p * v3.y; a3.z += p * v3.z; a3.w += p * v3.w;
        }
        a0.x = tf32_rna(a0.x); a0.y = tf32_rna(a0.y); a0.z = tf32_rna(a0.z); a0.w = tf32_rna(a0.w);
        a1.x = tf32_rna(a1.x); a1.y = tf32_rna(a1.y); a1.z = tf32_rna(a1.z); a1.w = tf32_rna(a1.w);
        a2.x = tf32_rna(a2.x); a2.y = tf32_rna(a2.y); a2.z = tf32_rna(a2.z); a2.w = tf32_rna(a2.w);
        a3.x = tf32_rna(a3.x); a3.y = tf32_rna(a3.y); a3.z = tf32_rna(a3.z); a3.w = tf32_rna(a3.w);
        ((float4*)g_vmix)[(rb + 0) * (HH / 4) + tid] = a0;
        ((float4*)g_vmix)[(rb + 1) * (HH / 4) + tid] = a1;
        ((float4*)g_vmix)[(rb + 2) * (HH / 4) + tid] = a2;
        ((float4*)g_vmix)[(rb + 3) * (HH / 4) + tid] = a3;
    }
}

// ---------------- 5) GEMM: out = vmix @ Wv^T + bv (tf32 mma.sync) -----------
// 3-stage cp.async pipeline, BK=32, cp.async issues interleaved with compute.
#define BM 128
#define BN 128
#define BK 32
#define LDA 36                 // padded smem stride: bank = 4*grp+qid, conflict-free
#define KT (HH / BK)           // 32
#define NST 3
#define STG_A (BM * LDA)       // floats per A stage
#define STG_B (BN * LDA)
#define GSMEM (NST * (STG_A + STG_B) * 4)   // 110592 bytes

__device__ __forceinline__ void cp_async16(uint32_t s, const void* g) {
    asm volatile("cp.async.cg.shared.global [%0], [%1], 16;" :: "r"(s), "l"(g));
}

__global__ __launch_bounds__(256, 2) void k_gemm(const float* __restrict__ bias,
                                                 float* __restrict__ C) {
    extern __shared__ float smemf[];
    float* As = smemf;                  // [NST][STG_A]
    float* Bs = smemf + NST * STG_A;    // [NST][STG_B]
    const int tid = threadIdx.x;
    const int m0 = blockIdx.y * BM, n0 = blockIdx.x * BN;
    const int warp = tid >> 5, lane = tid & 31;
    const int wm = warp >> 2, wn = warp & 3;    // 2 x 4 warp grid
    const int grp = lane >> 2, qid = lane & 3;

    // cp.async addressing: rows r = (tid>>3) + 32k (k=0..3), col chunk = tid&7
    const int ldr = tid >> 3;            // 0..31
    const int ldc = (tid & 7) * 4;       // 0,4,...,28
    const float* Ag = g_vmix + (size_t)(m0 + ldr) * HH + ldc;
    const float* Bg = g_wvr + (size_t)(n0 + ldr) * HH + ldc;
    const uint32_t sa = (uint32_t)__cvta_generic_to_shared(&As[ldr * LDA + ldc]);
    const uint32_t sb = (uint32_t)__cvta_generic_to_shared(&Bs[ldr * LDA + ldc]);
    const uint32_t stA = sizeof(float) * STG_A;
    const uint32_t stB = sizeof(float) * STG_B;

    float acc[4][4][4];
    #pragma unroll
    for (int i = 0; i < 4; i++)
        #pragma unroll
        for (int j = 0; j < 4; j++)
            #pragma unroll
            for (int v = 0; v < 4; v++) acc[i][j][v] = 0.f;

    // prologue: stages 0 and 1 in flight
    #pragma unroll
    for (int s = 0; s < 2; s++) {
        const int kb = s * BK;
        #pragma unroll
        for (int k = 0; k < 4; k++) {
            cp_async16(sa + s * stA + k * 32 * LDA * 4, Ag + (size_t)k * 32 * HH + kb);
            cp_async16(sb + s * stB + k * 32 * LDA * 4, Bg + (size_t)k * 32 * HH + kb);
        }
        asm volatile("cp.async.commit_group;");
    }

    #pragma unroll 1
    for (int kt = 0; kt < KT; kt++) {
        const int st = kt % NST;
        asm volatile("cp.async.wait_group 1;");
        __syncthreads();   // stage (kt+2)%NST was consumed at iter kt-1 by all warps

        const int s2 = (kt + 2) % NST;
        const int kb2 = (kt + 2) * BK;
        const bool do_pf = (kt + 2 < KT);

        const uint32_t* as = (const uint32_t*)(As + st * STG_A);
        const uint32_t* bs = (const uint32_t*)(Bs + st * STG_B);
        #pragma unroll
        for (int ks = 0; ks < 4; ks++) {
            // interleave next-stage cp.async issue with compute (smooth smem port)
            if (do_pf) {
                cp_async16(sa + s2 * stA + ks * 32 * LDA * 4,
                           Ag + (size_t)ks * 32 * HH + kb2);
                cp_async16(sb + s2 * stB + ks * 32 * LDA * 4,
                           Bg + (size_t)ks * 32 * HH + kb2);
            }
            const int kc = ks * 8 + qid;
            uint32_t af[4][4], bf[4][2];
            #pragma unroll
            for (int mf = 0; mf < 4; mf++) {
                const int r = wm * 64 + mf * 16 + grp;
                af[mf][0] = as[r * LDA + kc];
                af[mf][1] = as[(r + 8) * LDA + kc];
                af[mf][2] = as[r * LDA + kc + 4];
                af[mf][3] = as[(r + 8) * LDA + kc + 4];
            }
            #pragma unroll
            for (int nf = 0; nf < 4; nf++) {
                const int n = wn * 32 + nf * 8 + grp;
                bf[nf][0] = bs[n * LDA + kc];
                bf[nf][1] = bs[n * LDA + kc + 4];
            }
            #pragma unroll
            for (int mf = 0; mf < 4; mf++)
                #pragma unroll
                for (int nf = 0; nf < 4; nf++) {
                    asm volatile(
                        "mma.sync.aligned.m16n8k8.row.col.f32.tf32.tf32.f32 "
                        "{%0,%1,%2,%3}, {%4,%5,%6,%7}, {%8,%9}, {%0,%1,%2,%3};"
                        : "+f"(acc[mf][nf][0]), "+f"(acc[mf][nf][1]),
                          "+f"(acc[mf][nf][2]), "+f"(acc[mf][nf][3])
                        : "r"(af[mf][0]), "r"(af[mf][1]), "r"(af[mf][2]), "r"(af[mf][3]),
                          "r"(bf[nf][0]), "r"(bf[nf][1]));
                }
        }
        asm volatile("cp.async.commit_group;");
    }

    // epilogue: + bias, float2 stores
    #pragma unroll
    for (int mf = 0; mf < 4; mf++) {
        const int r = m0 + wm * 64 + mf * 16 + grp;
        #pragma unroll
        for (int nf = 0; nf < 4; nf++) {
            const int c = n0 + wn * 32 + nf * 8 + qid * 2;
            const float b0v = __ldg(bias + c);
            const float b1v = __ldg(bias + c + 1);
            float2 v0 = make_float2(acc[mf][nf][0] + b0v, acc[mf][nf][1] + b1v);
            float2 v1 = make_float2(acc[mf][nf][2] + b0v, acc[mf][nf][3] + b1v);
            *(float2*)(C + (size_t)r * HH + c) = v0;
            *(float2*)(C + (size_t)(r + 8) * HH + c) = v1;
        }
    }
}

// ---------------- launch -----------------------------------------------------
extern "C" void kernel_launch(void* const* d_in, const int* in_sizes, int n_in,
                              void* d_out, int out_size) {
    (void)in_sizes; (void)n_in; (void)out_size;
    const float* query = (const float*)d_in[0];
    const float* key   = (const float*)d_in[1];
    const float* value = (const float*)d_in[2];
    const int*   amask = (const int*)d_in[3];
    const float* Wq    = (const float*)d_in[4];
    const float* bq    = (const float*)d_in[5];
    const float* Wk    = (const float*)d_in[6];
    const float* bk    = (const float*)d_in[7];
    const float* Wv    = (const float*)d_in[8];
    const float* bv    = (const float*)d_in[9];
    float* out = (float*)d_out;

    cudaFuncSetAttribute(k_gemm, cudaFuncAttributeMaxDynamicSharedMemorySize, GSMEM);

    k_pool_round<<<BB * CH + HH * HH / (4 * 256), 256>>>(query, key, amask, Wv);
    k_combine<<<12, 256>>>();
    k_enc<<<80, 256>>>(Wq, bq, Wk, bk);
    k_vmix<<<BB * SS / 16, 256>>>(value);
    k_gemm<<<dim3(HH / BN, BB * SS / BM), 256, GSMEM>>>(bv, out);
}